// round 1
// baseline (speedup 1.0000x reference)
#include <cuda_runtime.h>
#include <math.h>

#define NTOK 8192
#define HDIM 1024
#define FDIM 4096
#define NEXP 8
#define NROWS (NTOK*2)

// ---------------- device scratch (allocation-free) ----------------
__device__ int   g_cnt[NEXP];
__device__ int   g_fill[NEXP];
__device__ int   g_off[NEXP+1];
__device__ int   g_tp[NEXP+1];              // row-tile prefix per expert
__device__ int   g_tok_e[NTOK*2];
__device__ float g_tok_w[NTOK*2];
__device__ int   g_row_token[NROWS];
__device__ float g_row_weight[NROWS];
__device__ float g_hidden[(size_t)NROWS*FDIM];   // 268 MB grouped hidden

// ---------------- small kernels ----------------
__global__ void k_init() {
    int i = threadIdx.x;
    if (i < NEXP) { g_cnt[i] = 0; g_fill[i] = 0; }
}

__global__ void k_zero_out(float* out) {
    size_t i = (size_t)blockIdx.x * blockDim.x + threadIdx.x;
    size_t n = (size_t)NTOK * HDIM / 4;
    if (i < n) ((float4*)out)[i] = make_float4(0.f, 0.f, 0.f, 0.f);
}

__global__ void k_router(const float* __restrict__ x,
                         const float* __restrict__ rw,
                         const float* __restrict__ rb) {
    int warp = (blockIdx.x * blockDim.x + threadIdx.x) >> 5;
    int lane = threadIdx.x & 31;
    if (warp >= NTOK) return;
    const float* xr = x + (size_t)warp * HDIM;
    float acc[NEXP];
#pragma unroll
    for (int e = 0; e < NEXP; e++) acc[e] = 0.f;
    for (int h = lane; h < HDIM; h += 32) {
        float xv = __ldg(xr + h);
#pragma unroll
        for (int e = 0; e < NEXP; e++)
            acc[e] = fmaf(xv, __ldg(rw + e * HDIM + h), acc[e]);
    }
#pragma unroll
    for (int o = 16; o > 0; o >>= 1)
#pragma unroll
        for (int e = 0; e < NEXP; e++)
            acc[e] += __shfl_xor_sync(0xffffffffu, acc[e], o);
    if (lane == 0) {
        float l[NEXP];
#pragma unroll
        for (int e = 0; e < NEXP; e++) l[e] = acc[e] + rb[e];
        int i0 = 0; float b0 = l[0];
#pragma unroll
        for (int e = 1; e < NEXP; e++) if (l[e] > b0) { b0 = l[e]; i0 = e; }
        int i1 = (i0 == 0) ? 1 : 0; float b1 = -3.4e38f;
#pragma unroll
        for (int e = 0; e < NEXP; e++)
            if (e != i0 && l[e] > b1) { b1 = l[e]; i1 = e; }
        // normalized top-2 softmax weights: p0/(p0+p1) = 1/(1+exp(l1-l0))
        float w0 = 1.f / (1.f + expf(b1 - b0));
        g_tok_e[warp*2]   = i0;  g_tok_e[warp*2+1] = i1;
        g_tok_w[warp*2]   = w0;  g_tok_w[warp*2+1] = 1.f - w0;
        atomicAdd(&g_cnt[i0], 1);
        atomicAdd(&g_cnt[i1], 1);
    }
}

__global__ void k_offsets() {
    g_off[0] = 0; g_tp[0] = 0;
    for (int e = 0; e < NEXP; e++) {
        g_off[e+1] = g_off[e] + g_cnt[e];
        g_tp[e+1]  = g_tp[e]  + (g_cnt[e] + 127) / 128;
    }
}

__global__ void k_scatter() {
    int i = blockIdx.x * blockDim.x + threadIdx.x;
    if (i >= NTOK * 2) return;
    int e = g_tok_e[i];
    int r = g_off[e] + atomicAdd(&g_fill[e], 1);
    g_row_token[r]  = i >> 1;
    g_row_weight[r] = g_tok_w[i];
}

// ---------------- grouped GEMM: 128x128x8 fp32 SIMT, double-buffered ----------------
// MODE 1: A = x gathered by token, epilogue = exact GELU -> g_hidden
// MODE 2: A = g_hidden (direct grouped rows), epilogue = weight * atomicAdd -> out
template<int KDIM, int NDIM, int MODE>
__global__ void __launch_bounds__(256, 2)
k_gemm(const float* __restrict__ Asrc,
       const float* __restrict__ Wsrc,
       float* __restrict__ out) {
    const int colTiles = NDIM / 128;
    int totalRT = g_tp[NEXP];
    int t = blockIdx.x;
    if (t >= totalRT * colTiles) return;
    int rt = t % totalRT;
    int ct = t / totalRT;
    int e = 0;
    while (g_tp[e+1] <= rt) e++;
    int row0   = g_off[e] + (rt - g_tp[e]) * 128;
    int rowEnd = g_off[e+1];
    int n0 = ct * 128;
    const float* B = Wsrc + (size_t)e * KDIM * NDIM;

    __shared__ float As[2][8][128];
    __shared__ float Bs[2][8][128];

    int tid = threadIdx.x;
    int arow = tid >> 1, ak = (tid & 1) * 4;
    int bk = tid >> 5,  bn = (tid & 31) * 4;
    int tx = tid & 15,  ty = tid >> 4;
    int tm0 = ty * 8,   tn0 = tx * 8;

    // per-thread A row base (guarded gather)
    const float* arp = nullptr;
    {
        int gr = row0 + arow;
        if (gr < rowEnd) {
            if (MODE == 1) arp = Asrc + (size_t)g_row_token[gr] * KDIM;
            else           arp = g_hidden + (size_t)gr * KDIM;
        }
    }
    const float* brp = B + (size_t)bk * NDIM + n0 + bn;

    float acc[8][8];
#pragma unroll
    for (int i = 0; i < 8; i++)
#pragma unroll
        for (int j = 0; j < 8; j++) acc[i][j] = 0.f;

    // stage 0
    {
        float4 av = make_float4(0.f, 0.f, 0.f, 0.f);
        if (arp) av = *(const float4*)(arp + ak);
        float4 bv = *(const float4*)(brp);
        As[0][ak+0][arow] = av.x; As[0][ak+1][arow] = av.y;
        As[0][ak+2][arow] = av.z; As[0][ak+3][arow] = av.w;
        *(float4*)&Bs[0][bk][bn] = bv;
    }
    __syncthreads();

    const int NKB = KDIM / 8;
    for (int kb = 0; kb < NKB; kb++) {
        int s = kb & 1;
        float4 avn = make_float4(0.f, 0.f, 0.f, 0.f), bvn;
        if (kb + 1 < NKB) {
            if (arp) avn = *(const float4*)(arp + (kb+1)*8 + ak);
            bvn = *(const float4*)(brp + (size_t)(kb+1)*8*NDIM);
        }
#pragma unroll
        for (int kk = 0; kk < 8; kk++) {
            float a[8], b[8];
            *(float4*)&a[0] = *(float4*)&As[s][kk][tm0];
            *(float4*)&a[4] = *(float4*)&As[s][kk][tm0+4];
            *(float4*)&b[0] = *(float4*)&Bs[s][kk][tn0];
            *(float4*)&b[4] = *(float4*)&Bs[s][kk][tn0+4];
#pragma unroll
            for (int i = 0; i < 8; i++)
#pragma unroll
                for (int j = 0; j < 8; j++)
                    acc[i][j] = fmaf(a[i], b[j], acc[i][j]);
        }
        if (kb + 1 < NKB) {
            int s2 = s ^ 1;
            As[s2][ak+0][arow] = avn.x; As[s2][ak+1][arow] = avn.y;
            As[s2][ak+2][arow] = avn.z; As[s2][ak+3][arow] = avn.w;
            *(float4*)&Bs[s2][bk][bn] = bvn;
        }
        __syncthreads();
    }

    // epilogue
#pragma unroll
    for (int i = 0; i < 8; i++) {
        int gr = row0 + tm0 + i;
        if (gr >= rowEnd) continue;
        if (MODE == 1) {
            float* hp = g_hidden + (size_t)gr * NDIM + n0 + tn0;
#pragma unroll
            for (int j = 0; j < 8; j++) {
                float v = acc[i][j];
                hp[j] = 0.5f * v * (1.f + erff(v * 0.70710678118654752f));
            }
        } else {
            int tok = g_row_token[gr];
            float w = g_row_weight[gr];
            float* op = out + (size_t)tok * NDIM + n0 + tn0;
#pragma unroll
            for (int j = 0; j < 8; j++)
                atomicAdd(op + j, acc[i][j] * w);
        }
    }
}

// ---------------- launch ----------------
extern "C" void kernel_launch(void* const* d_in, const int* in_sizes, int n_in,
                              void* d_out, int out_size) {
    const float* x  = (const float*)d_in[0];
    const float* rw = (const float*)d_in[1];
    const float* rb = (const float*)d_in[2];
    const float* w1 = (const float*)d_in[3];
    const float* w2 = (const float*)d_in[4];
    float* out = (float*)d_out;

    k_init<<<1, 32>>>();
    k_zero_out<<<(NTOK*HDIM/4 + 255)/256, 256>>>(out);
    k_router<<<NTOK/8, 256>>>(x, rw, rb);
    k_offsets<<<1, 1>>>();
    k_scatter<<<(NTOK*2 + 255)/256, 256>>>();

    // worst-case row tiles: 16384/128 + 8 rounding = 136
    k_gemm<HDIM, FDIM, 1><<<136*32, 256>>>(x, w1, nullptr);
    k_gemm<FDIM, HDIM, 2><<<136*8, 256>>>(nullptr, w2, out);
}

// round 2
// speedup vs baseline: 4.3879x; 4.3879x over previous
#include <cuda_runtime.h>
#include <cuda_fp16.h>
#include <cstdint>
#include <math.h>

#define NTOK 8192
#define HDIM 1024
#define FDIM 4096
#define NEXP 8
#define NROWS (NTOK*2)

// ---------------- device scratch (allocation-free) ----------------
__device__ int    g_cnt[NEXP];
__device__ int    g_fill[NEXP];
__device__ int    g_off[NEXP+1];
__device__ int    g_tp[NEXP+1];
__device__ int    g_tok_e[NTOK*2];
__device__ float  g_tok_w[NTOK*2];
__device__ int    g_row_token[NROWS];
__device__ float  g_row_weight[NROWS];
__device__ __half g_hidden[(size_t)NROWS*FDIM];   // 134 MB grouped hidden (fp16)

// ---------------- small kernels ----------------
__global__ void k_init() {
    int i = threadIdx.x;
    if (i < NEXP) { g_cnt[i] = 0; g_fill[i] = 0; }
}

__global__ void k_zero_out(float* out) {
    size_t i = (size_t)blockIdx.x * blockDim.x + threadIdx.x;
    size_t n = (size_t)NTOK * HDIM / 4;
    if (i < n) ((float4*)out)[i] = make_float4(0.f, 0.f, 0.f, 0.f);
}

__global__ void k_router(const float* __restrict__ x,
                         const float* __restrict__ rw,
                         const float* __restrict__ rb) {
    int warp = (blockIdx.x * blockDim.x + threadIdx.x) >> 5;
    int lane = threadIdx.x & 31;
    if (warp >= NTOK) return;
    const float* xr = x + (size_t)warp * HDIM;
    float acc[NEXP];
#pragma unroll
    for (int e = 0; e < NEXP; e++) acc[e] = 0.f;
    for (int h = lane; h < HDIM; h += 32) {
        float xv = __ldg(xr + h);
#pragma unroll
        for (int e = 0; e < NEXP; e++)
            acc[e] = fmaf(xv, __ldg(rw + e * HDIM + h), acc[e]);
    }
#pragma unroll
    for (int o = 16; o > 0; o >>= 1)
#pragma unroll
        for (int e = 0; e < NEXP; e++)
            acc[e] += __shfl_xor_sync(0xffffffffu, acc[e], o);
    if (lane == 0) {
        float l[NEXP];
#pragma unroll
        for (int e = 0; e < NEXP; e++) l[e] = acc[e] + rb[e];
        int i0 = 0; float b0 = l[0];
#pragma unroll
        for (int e = 1; e < NEXP; e++) if (l[e] > b0) { b0 = l[e]; i0 = e; }
        int i1 = (i0 == 0) ? 1 : 0; float b1 = -3.4e38f;
#pragma unroll
        for (int e = 0; e < NEXP; e++)
            if (e != i0 && l[e] > b1) { b1 = l[e]; i1 = e; }
        float w0 = 1.f / (1.f + expf(b1 - b0));
        g_tok_e[warp*2]   = i0;  g_tok_e[warp*2+1] = i1;
        g_tok_w[warp*2]   = w0;  g_tok_w[warp*2+1] = 1.f - w0;
        atomicAdd(&g_cnt[i0], 1);
        atomicAdd(&g_cnt[i1], 1);
    }
}

__global__ void k_offsets() {
    g_off[0] = 0; g_tp[0] = 0;
    for (int e = 0; e < NEXP; e++) {
        g_off[e+1] = g_off[e] + g_cnt[e];
        g_tp[e+1]  = g_tp[e]  + (g_cnt[e] + 127) / 128;
    }
}

__global__ void k_scatter() {
    int i = blockIdx.x * blockDim.x + threadIdx.x;
    if (i >= NTOK * 2) return;
    int e = g_tok_e[i];
    int r = g_off[e] + atomicAdd(&g_fill[e], 1);
    g_row_token[r]  = i >> 1;
    g_row_weight[r] = g_tok_w[i];
}

// ---------------- tensor-core grouped GEMM (fp16 in, fp32 accum) ----------------
#define BM 128
#define BN 128
#define BK 32
#define LDAs 40    // fp16 elems per A smem row (80B stride -> conflict-free LDSM)
#define LDBs 136   // fp16 elems per B smem row (272B stride -> conflict-free LDSM)

__device__ __forceinline__ void ldsm_x4(uint32_t& r0, uint32_t& r1, uint32_t& r2, uint32_t& r3, uint32_t a) {
    asm volatile("ldmatrix.sync.aligned.m8n8.x4.shared.b16 {%0,%1,%2,%3},[%4];"
                 : "=r"(r0), "=r"(r1), "=r"(r2), "=r"(r3) : "r"(a));
}
__device__ __forceinline__ void ldsm_x4t(uint32_t& r0, uint32_t& r1, uint32_t& r2, uint32_t& r3, uint32_t a) {
    asm volatile("ldmatrix.sync.aligned.m8n8.x4.trans.shared.b16 {%0,%1,%2,%3},[%4];"
                 : "=r"(r0), "=r"(r1), "=r"(r2), "=r"(r3) : "r"(a));
}
__device__ __forceinline__ void mma16816(float* c, const uint32_t* a, const uint32_t* b) {
    asm volatile("mma.sync.aligned.m16n8k16.row.col.f32.f16.f16.f32 "
                 "{%0,%1,%2,%3},{%4,%5,%6,%7},{%8,%9},{%0,%1,%2,%3};"
                 : "+f"(c[0]), "+f"(c[1]), "+f"(c[2]), "+f"(c[3])
                 : "r"(a[0]), "r"(a[1]), "r"(a[2]), "r"(a[3]), "r"(b[0]), "r"(b[1]));
}
__device__ __forceinline__ float gelu_exact(float v) {
    return 0.5f * v * (1.f + erff(v * 0.70710678118654752f));
}

// MODE 1: A = x (fp32, gathered by token)  -> GELU -> g_hidden (fp16)
// MODE 2: A = g_hidden (fp16, grouped rows) -> weight*atomicAdd -> out (fp32)
template<int KDIM, int NDIM, int MODE>
__global__ void __launch_bounds__(256, 1)
k_gemm_tc(const float* __restrict__ Asrc,
          const float* __restrict__ Wsrc,
          float* __restrict__ out)
{
    const int colTiles = NDIM / BN;
    int totalRT = g_tp[NEXP];
    int t = blockIdx.x;
    if (t >= totalRT * colTiles) return;
    int rt = t % totalRT;
    int ct = t / totalRT;
    int e = 0;
    while (g_tp[e+1] <= rt) e++;
    int row0   = g_off[e] + (rt - g_tp[e]) * BM;
    int rowEnd = g_off[e+1];
    int n0 = ct * BN;
    const float* Bg = Wsrc + (size_t)e * KDIM * NDIM;

    __shared__ __half As[2][BM][LDAs];
    __shared__ __half Bs[2][BK][LDBs];

    int tid  = threadIdx.x;
    int lane = tid & 31;
    int wid  = tid >> 5;
    int wm   = wid >> 2;     // 0..1 -> 64 rows each
    int wn   = wid & 3;      // 0..3 -> 32 cols each

    // A global loader: 4 passes of 32 rows; each thread: 4 consecutive k
    int arow_l = tid >> 3;             // 0..31
    int akv    = (tid & 7) * 4;        // 0..28
    const float*  aptrF[4];
    const __half* aptrH[4];
    bool avalid[4];
#pragma unroll
    for (int p = 0; p < 4; p++) {
        int gr = row0 + arow_l + 32 * p;
        avalid[p] = (gr < rowEnd);
        int tok = avalid[p] ? (MODE == 1 ? g_row_token[gr] : gr) : 0;
        if (MODE == 1) aptrF[p] = Asrc + (size_t)tok * KDIM + akv;
        else           aptrH[p] = g_hidden + (size_t)tok * KDIM + akv;
    }
    // B global loader: 4 passes of 8 k-rows; each thread: 4 consecutive n
    int bkr = tid >> 5;                // 0..7
    int bnv = (tid & 31) * 4;          // 0..124
    const float* bptr = Bg + (size_t)bkr * NDIM + n0 + bnv;

    float acc[4][4][4];
#pragma unroll
    for (int mi = 0; mi < 4; mi++)
#pragma unroll
        for (int ni = 0; ni < 4; ni++)
#pragma unroll
            for (int k = 0; k < 4; k++) acc[mi][ni][k] = 0.f;

    // ---- stage 0 direct load ----
#pragma unroll
    for (int p = 0; p < 4; p++) {
        int r = arow_l + 32 * p;
        if (MODE == 1) {
            float4 v = make_float4(0.f, 0.f, 0.f, 0.f);
            if (avalid[p]) v = *(const float4*)(aptrF[p]);
            *(__half2*)&As[0][r][akv]     = __floats2half2_rn(v.x, v.y);
            *(__half2*)&As[0][r][akv + 2] = __floats2half2_rn(v.z, v.w);
        } else {
            uint2 v = make_uint2(0u, 0u);
            if (avalid[p]) v = *(const uint2*)(aptrH[p]);
            *(uint2*)&As[0][r][akv] = v;
        }
    }
#pragma unroll
    for (int p = 0; p < 4; p++) {
        float4 v = *(const float4*)(bptr + (size_t)p * 8 * NDIM);
        int r = bkr + 8 * p;
        *(__half2*)&Bs[0][r][bnv]     = __floats2half2_rn(v.x, v.y);
        *(__half2*)&Bs[0][r][bnv + 2] = __floats2half2_rn(v.z, v.w);
    }
    __syncthreads();

    const int NKB = KDIM / BK;
    for (int kb = 0; kb < NKB; kb++) {
        int s = kb & 1;
        // prefetch next stage into registers
        float4 pfA[4]; uint2 pfAh[4]; float4 pfB[4];
        if (kb + 1 < NKB) {
            int koff = (kb + 1) * BK;
#pragma unroll
            for (int p = 0; p < 4; p++) {
                if (MODE == 1) {
                    pfA[p] = make_float4(0.f, 0.f, 0.f, 0.f);
                    if (avalid[p]) pfA[p] = *(const float4*)(aptrF[p] + koff);
                } else {
                    pfAh[p] = make_uint2(0u, 0u);
                    if (avalid[p]) pfAh[p] = *(const uint2*)(aptrH[p] + koff);
                }
            }
#pragma unroll
            for (int p = 0; p < 4; p++)
                pfB[p] = *(const float4*)(bptr + ((size_t)koff + p * 8) * NDIM);
        }
        // ---- compute 2 k-steps of 16 ----
#pragma unroll
        for (int kk = 0; kk < 2; kk++) {
            int k0 = kk * 16;
            uint32_t afr[4][4];
#pragma unroll
            for (int mi = 0; mi < 4; mi++) {
                int r = wm * 64 + mi * 16 + (lane & 15);
                int c = k0 + (lane >> 4) * 8;
                uint32_t addr = (uint32_t)__cvta_generic_to_shared(&As[s][r][c]);
                ldsm_x4(afr[mi][0], afr[mi][1], afr[mi][2], afr[mi][3], addr);
            }
            uint32_t bfr[4][2];
#pragma unroll
            for (int nb = 0; nb < 2; nb++) {
                int kr = k0 + (lane & 15);
                int c  = wn * 32 + nb * 16 + (lane >> 4) * 8;
                uint32_t addr = (uint32_t)__cvta_generic_to_shared(&Bs[s][kr][c]);
                uint32_t r0, r1, r2, r3;
                ldsm_x4t(r0, r1, r2, r3, addr);
                bfr[nb * 2][0] = r0;  bfr[nb * 2][1] = r1;
                bfr[nb * 2 + 1][0] = r2;  bfr[nb * 2 + 1][1] = r3;
            }
#pragma unroll
            for (int mi = 0; mi < 4; mi++)
#pragma unroll
                for (int ni = 0; ni < 4; ni++)
                    mma16816(acc[mi][ni], afr[mi], bfr[ni]);
        }
        // ---- store prefetched stage ----
        if (kb + 1 < NKB) {
            int s2 = s ^ 1;
#pragma unroll
            for (int p = 0; p < 4; p++) {
                int r = arow_l + 32 * p;
                if (MODE == 1) {
                    *(__half2*)&As[s2][r][akv]     = __floats2half2_rn(pfA[p].x, pfA[p].y);
                    *(__half2*)&As[s2][r][akv + 2] = __floats2half2_rn(pfA[p].z, pfA[p].w);
                } else {
                    *(uint2*)&As[s2][r][akv] = pfAh[p];
                }
            }
#pragma unroll
            for (int p = 0; p < 4; p++) {
                int r = bkr + 8 * p;
                *(__half2*)&Bs[s2][r][bnv]     = __floats2half2_rn(pfB[p].x, pfB[p].y);
                *(__half2*)&Bs[s2][r][bnv + 2] = __floats2half2_rn(pfB[p].z, pfB[p].w);
            }
        }
        __syncthreads();
    }

    // ---- epilogue ----
    int mrow = row0 + wm * 64 + (lane >> 2);
    int ncol = n0 + wn * 32 + (lane & 3) * 2;
#pragma unroll
    for (int mi = 0; mi < 4; mi++) {
#pragma unroll
        for (int ni = 0; ni < 4; ni++) {
            int r0r = mrow + mi * 16;
            int c   = ncol + ni * 8;
            if (MODE == 1) {
                if (r0r < rowEnd) {
                    __half2 h = __floats2half2_rn(gelu_exact(acc[mi][ni][0]),
                                                  gelu_exact(acc[mi][ni][1]));
                    *(__half2*)&g_hidden[(size_t)r0r * NDIM + c] = h;
                }
                if (r0r + 8 < rowEnd) {
                    __half2 h = __floats2half2_rn(gelu_exact(acc[mi][ni][2]),
                                                  gelu_exact(acc[mi][ni][3]));
                    *(__half2*)&g_hidden[(size_t)(r0r + 8) * NDIM + c] = h;
                }
            } else {
                if (r0r < rowEnd) {
                    int tok = g_row_token[r0r];
                    float w = g_row_weight[r0r];
                    atomicAdd(out + (size_t)tok * NDIM + c,     acc[mi][ni][0] * w);
                    atomicAdd(out + (size_t)tok * NDIM + c + 1, acc[mi][ni][1] * w);
                }
                if (r0r + 8 < rowEnd) {
                    int tok = g_row_token[r0r + 8];
                    float w = g_row_weight[r0r + 8];
                    atomicAdd(out + (size_t)tok * NDIM + c,     acc[mi][ni][2] * w);
                    atomicAdd(out + (size_t)tok * NDIM + c + 1, acc[mi][ni][3] * w);
                }
            }
        }
    }
}

// ---------------- launch ----------------
extern "C" void kernel_launch(void* const* d_in, const int* in_sizes, int n_in,
                              void* d_out, int out_size) {
    const float* x  = (const float*)d_in[0];
    const float* rw = (const float*)d_in[1];
    const float* rb = (const float*)d_in[2];
    const float* w1 = (const float*)d_in[3];
    const float* w2 = (const float*)d_in[4];
    float* out = (float*)d_out;

    k_init<<<1, 32>>>();
    k_zero_out<<<(NTOK*HDIM/4 + 255)/256, 256>>>(out);
    k_router<<<NTOK/8, 256>>>(x, rw, rb);
    k_offsets<<<1, 1>>>();
    k_scatter<<<(NTOK*2 + 255)/256, 256>>>();

    // worst-case row tiles: 16384/128 + 8 (per-expert rounding) = 136
    k_gemm_tc<HDIM, FDIM, 1><<<136*32, 256>>>(x, w1, nullptr);
    k_gemm_tc<FDIM, HDIM, 2><<<136*8, 256>>>(nullptr, w2, out);
}

// round 4
// speedup vs baseline: 5.4196x; 1.2351x over previous
#include <cuda_runtime.h>
#include <cuda_fp16.h>
#include <cstdint>
#include <math.h>

#define NTOK 8192
#define HDIM 1024
#define FDIM 4096
#define NEXP 8
#define NROWS (NTOK*2)

// ---------------- device scratch (allocation-free) ----------------
__device__ int    g_cnt[NEXP];
__device__ int    g_fill[NEXP];
__device__ int    g_off[NEXP+1];
__device__ int    g_tp[NEXP+1];
__device__ int    g_tok_e[NTOK*2];
__device__ float  g_tok_w[NTOK*2];
__device__ int    g_pos[NTOK*2];                  // grouped row index per (token,slot)
__device__ int    g_row_token[NROWS];
__device__ __half g_hidden[(size_t)NROWS*FDIM];   // 134 MB grouped hidden (fp16)
__device__ __half g_xh[(size_t)NTOK*HDIM];        // x fp16
__device__ __half g_w1h[(size_t)NEXP*HDIM*FDIM];  // w1 fp16 (natural [e][H][F])
__device__ __half g_w2h[(size_t)NEXP*FDIM*HDIM];  // w2 fp16 (natural [e][F][H])
__device__ float  g_eout[(size_t)NROWS*HDIM];     // per-row GEMM2 output fp32

// ---------------- helpers ----------------
__device__ __forceinline__ uint32_t smem_u32(const void* p) {
    uint32_t a;
    asm("{ .reg .u64 t; cvta.to.shared.u64 t, %1; cvt.u32.u64 %0, t; }" : "=r"(a) : "l"(p));
    return a;
}
#define CPA16(dst,src,sz) asm volatile("cp.async.cg.shared.global [%0],[%1],16,%2;" :: "r"(dst), "l"(src), "r"(sz))
#define CPA_COMMIT() asm volatile("cp.async.commit_group;" ::: "memory")
#define CPA_WAIT1()  asm volatile("cp.async.wait_group 1;" ::: "memory")

__device__ __forceinline__ void ldsm_x4(uint32_t& r0, uint32_t& r1, uint32_t& r2, uint32_t& r3, uint32_t a) {
    asm volatile("ldmatrix.sync.aligned.m8n8.x4.shared.b16 {%0,%1,%2,%3},[%4];"
                 : "=r"(r0), "=r"(r1), "=r"(r2), "=r"(r3) : "r"(a));
}
__device__ __forceinline__ void ldsm_x4t(uint32_t& r0, uint32_t& r1, uint32_t& r2, uint32_t& r3, uint32_t a) {
    asm volatile("ldmatrix.sync.aligned.m8n8.x4.trans.shared.b16 {%0,%1,%2,%3},[%4];"
                 : "=r"(r0), "=r"(r1), "=r"(r2), "=r"(r3) : "r"(a));
}
__device__ __forceinline__ void mma16816(float* c, const uint32_t* a, const uint32_t* b) {
    asm volatile("mma.sync.aligned.m16n8k16.row.col.f32.f16.f16.f32 "
                 "{%0,%1,%2,%3},{%4,%5,%6,%7},{%8,%9},{%0,%1,%2,%3};"
                 : "+f"(c[0]), "+f"(c[1]), "+f"(c[2]), "+f"(c[3])
                 : "r"(a[0]), "r"(a[1]), "r"(a[2]), "r"(a[3]), "r"(b[0]), "r"(b[1]));
}
__device__ __forceinline__ float gelu_exact(float v) {
    return 0.5f * v * (1.f + erff(v * 0.70710678118654752f));
}

// ---------------- small kernels ----------------
__global__ void k_init() {
    int i = threadIdx.x;
    if (i < NEXP) { g_cnt[i] = 0; g_fill[i] = 0; }
}
__global__ void k_convert_x(const float* __restrict__ x) {
    size_t i = (size_t)blockIdx.x * blockDim.x + threadIdx.x;
    if (i < (size_t)NTOK * HDIM / 4) {
        float4 v = ((const float4*)x)[i];
        __half2 a = __floats2half2_rn(v.x, v.y);
        __half2 b = __floats2half2_rn(v.z, v.w);
        ((uint2*)g_xh)[i] = make_uint2(*(uint32_t*)&a, *(uint32_t*)&b);
    }
}
__global__ void k_convert_w(const float4* __restrict__ src, uint2* __restrict__ dst, int n4) {
    int i = blockIdx.x * blockDim.x + threadIdx.x;
    if (i < n4) {
        float4 v = src[i];
        __half2 a = __floats2half2_rn(v.x, v.y);
        __half2 b = __floats2half2_rn(v.z, v.w);
        dst[i] = make_uint2(*(uint32_t*)&a, *(uint32_t*)&b);
    }
}

__global__ void k_router(const float* __restrict__ x,
                         const float* __restrict__ rw,
                         const float* __restrict__ rb) {
    int warp = (blockIdx.x * blockDim.x + threadIdx.x) >> 5;
    int lane = threadIdx.x & 31;
    if (warp >= NTOK) return;
    const float* xr = x + (size_t)warp * HDIM;
    float acc[NEXP];
#pragma unroll
    for (int e = 0; e < NEXP; e++) acc[e] = 0.f;
    for (int h = lane; h < HDIM; h += 32) {
        float xv = __ldg(xr + h);
#pragma unroll
        for (int e = 0; e < NEXP; e++)
            acc[e] = fmaf(xv, __ldg(rw + e * HDIM + h), acc[e]);
    }
#pragma unroll
    for (int o = 16; o > 0; o >>= 1)
#pragma unroll
        for (int e = 0; e < NEXP; e++)
            acc[e] += __shfl_xor_sync(0xffffffffu, acc[e], o);
    if (lane == 0) {
        float l[NEXP];
#pragma unroll
        for (int e = 0; e < NEXP; e++) l[e] = acc[e] + rb[e];
        int i0 = 0; float b0 = l[0];
#pragma unroll
        for (int e = 1; e < NEXP; e++) if (l[e] > b0) { b0 = l[e]; i0 = e; }
        int i1 = (i0 == 0) ? 1 : 0; float b1 = -3.4e38f;
#pragma unroll
        for (int e = 0; e < NEXP; e++)
            if (e != i0 && l[e] > b1) { b1 = l[e]; i1 = e; }
        float w0 = 1.f / (1.f + expf(b1 - b0));
        g_tok_e[warp*2]   = i0;  g_tok_e[warp*2+1] = i1;
        g_tok_w[warp*2]   = w0;  g_tok_w[warp*2+1] = 1.f - w0;
        atomicAdd(&g_cnt[i0], 1);
        atomicAdd(&g_cnt[i1], 1);
    }
}
__global__ void k_offsets() {
    g_off[0] = 0; g_tp[0] = 0;
    for (int e = 0; e < NEXP; e++) {
        g_off[e+1] = g_off[e] + g_cnt[e];
        g_tp[e+1]  = g_tp[e]  + (g_cnt[e] + 127) / 128;
    }
}
__global__ void k_scatter() {
    int i = blockIdx.x * blockDim.x + threadIdx.x;
    if (i >= NTOK * 2) return;
    int e = g_tok_e[i];
    int r = g_off[e] + atomicAdd(&g_fill[e], 1);
    g_row_token[r] = i >> 1;
    g_pos[i] = r;
}
__global__ void k_combine(float* __restrict__ out) {
    int idx = blockIdx.x * blockDim.x + threadIdx.x;
    if (idx >= NTOK * HDIM / 4) return;
    int tok = idx / (HDIM / 4);
    int c4  = idx % (HDIM / 4);
    float w0 = g_tok_w[tok*2], w1 = g_tok_w[tok*2+1];
    int   r0 = g_pos[tok*2],  r1 = g_pos[tok*2+1];
    float4 a = ((const float4*)(g_eout + (size_t)r0 * HDIM))[c4];
    float4 b = ((const float4*)(g_eout + (size_t)r1 * HDIM))[c4];
    float4 o;
    o.x = w0 * a.x + w1 * b.x;  o.y = w0 * a.y + w1 * b.y;
    o.z = w0 * a.z + w1 * b.z;  o.w = w0 * a.w + w1 * b.w;
    ((float4*)out)[idx] = o;
}

// ---------------- grouped GEMM: 128x128x64, cp.async 3-stage, mma.sync fp16 ----------------
#define BK 64
#define LDA 72      // fp16/row (144B, odd multiple of 16B -> conflict-free)
#define LDB 136     // fp16/row (272B)
#define STG_A (128*LDA*2)
#define STG_B (BK*LDB*2)
#define STG   (STG_A + STG_B)
#define SMEM_BYTES (3*STG)

// MODE 1: A = g_xh gathered by token, B = g_w1h -> GELU -> g_hidden (fp16)
// MODE 2: A = g_hidden grouped rows,  B = g_w2h -> g_eout (fp32)
template<int KDIM, int NDIM, int MODE>
__global__ void __launch_bounds__(256, 2)
k_gemm_cp(float* __restrict__ dummy)
{
    extern __shared__ char smem[];
    uint32_t sb = smem_u32(smem);

    const int colTiles = NDIM / 128;
    int totalRT = g_tp[NEXP];
    int t = blockIdx.x;
    if (t >= totalRT * colTiles) return;
    int rt = t % totalRT;
    int ct = t / totalRT;
    int e = 0;
    while (g_tp[e+1] <= rt) e++;
    int row0   = g_off[e] + (rt - g_tp[e]) * 128;
    int rowEnd = g_off[e+1];
    int n0 = ct * 128;

    const __half* Wh = ((MODE == 1) ? g_w1h : g_w2h) + (size_t)e * KDIM * NDIM;

    int tid = threadIdx.x, lane = tid & 31, wid = tid >> 5;
    int wm = wid >> 2, wn = wid & 3;

    // ---- loaders ----
    int lrowA = tid >> 1;
    int asub  = (tid & 1) * 32;            // fp16 offset in row
    int gr = row0 + lrowA;
    bool av = (gr < rowEnd);
    const __half* asrc;
    if (MODE == 1) asrc = g_xh     + (size_t)(av ? g_row_token[gr] : 0) * KDIM + asub;
    else           asrc = g_hidden + (size_t)(av ? gr : 0) * KDIM + asub;
    int asz = av ? 16 : 0;

    int lrowB = tid >> 2;
    int bsub  = (tid & 3) * 32;
    const __half* bsrc = Wh + (size_t)lrowB * NDIM + n0 + bsub;

    uint32_t aDst[4], bDst[4];
#pragma unroll
    for (int i = 0; i < 4; i++) {
        aDst[i] = sb + (uint32_t)((lrowA * LDA + asub + i * 8) * 2);
        bDst[i] = sb + STG_A + (uint32_t)((lrowB * LDB + bsub + i * 8) * 2);
    }

    float acc[4][4][4];
#pragma unroll
    for (int mi = 0; mi < 4; mi++)
#pragma unroll
        for (int ni = 0; ni < 4; ni++)
#pragma unroll
            for (int k = 0; k < 4; k++) acc[mi][ni][k] = 0.f;

    const int NKB = KDIM / BK;

#define ISSUE(c) do { \
        uint32_t so = ((c) % 3) * STG; \
        const __half* as_ = asrc + (c) * BK; \
        const __half* bs_ = bsrc + (size_t)(c) * BK * NDIM; \
        _Pragma("unroll") \
        for (int i_ = 0; i_ < 4; i_++) CPA16(aDst[i_] + so, as_ + i_ * 8, asz); \
        _Pragma("unroll") \
        for (int i_ = 0; i_ < 4; i_++) CPA16(bDst[i_] + so, bs_ + (size_t)i_ * 8, 16); \
    } while(0)

    ISSUE(0); CPA_COMMIT();
    ISSUE(1); CPA_COMMIT();

    for (int kb = 0; kb < NKB; kb++) {
        CPA_WAIT1();
        __syncthreads();
        if (kb + 2 < NKB) ISSUE(kb + 2);
        CPA_COMMIT();

        uint32_t abase = sb + (kb % 3) * STG;
        uint32_t bbase = abase + STG_A;
#pragma unroll
        for (int kk = 0; kk < 4; kk++) {
            int k0 = kk * 16;
            uint32_t afr[4][4];
#pragma unroll
            for (int mi = 0; mi < 4; mi++) {
                uint32_t addr = abase + (uint32_t)(((wm * 64 + mi * 16 + (lane & 15)) * LDA
                                                    + k0 + (lane >> 4) * 8) * 2);
                ldsm_x4(afr[mi][0], afr[mi][1], afr[mi][2], afr[mi][3], addr);
            }
            uint32_t bfr[4][2];
#pragma unroll
            for (int nb = 0; nb < 2; nb++) {
                uint32_t addr = bbase + (uint32_t)(((k0 + (lane & 15)) * LDB
                                                    + wn * 32 + nb * 16 + (lane >> 4) * 8) * 2);
                uint32_t r0, r1, r2, r3;
                ldsm_x4t(r0, r1, r2, r3, addr);
                bfr[nb*2][0] = r0;   bfr[nb*2][1] = r1;
                bfr[nb*2+1][0] = r2; bfr[nb*2+1][1] = r3;
            }
#pragma unroll
            for (int mi = 0; mi < 4; mi++)
#pragma unroll
                for (int ni = 0; ni < 4; ni++)
                    mma16816(acc[mi][ni], afr[mi], bfr[ni]);
        }
        __syncthreads();
    }
#undef ISSUE

    // ---- epilogue ----
    int mrow = row0 + wm * 64 + (lane >> 2);
    int ncol = n0 + wn * 32 + (lane & 3) * 2;
#pragma unroll
    for (int mi = 0; mi < 4; mi++) {
#pragma unroll
        for (int ni = 0; ni < 4; ni++) {
            int r0r = mrow + mi * 16;
            int c   = ncol + ni * 8;
            if (MODE == 1) {
                if (r0r < rowEnd) {
                    __half2 h = __floats2half2_rn(gelu_exact(acc[mi][ni][0]),
                                                  gelu_exact(acc[mi][ni][1]));
                    *(__half2*)&g_hidden[(size_t)r0r * NDIM + c] = h;
                }
                if (r0r + 8 < rowEnd) {
                    __half2 h = __floats2half2_rn(gelu_exact(acc[mi][ni][2]),
                                                  gelu_exact(acc[mi][ni][3]));
                    *(__half2*)&g_hidden[(size_t)(r0r + 8) * NDIM + c] = h;
                }
            } else {
                if (r0r < rowEnd)
                    *(float2*)&g_eout[(size_t)r0r * NDIM + c] =
                        make_float2(acc[mi][ni][0], acc[mi][ni][1]);
                if (r0r + 8 < rowEnd)
                    *(float2*)&g_eout[(size_t)(r0r + 8) * NDIM + c] =
                        make_float2(acc[mi][ni][2], acc[mi][ni][3]);
            }
        }
    }
}

// ---------------- launch ----------------
extern "C" void kernel_launch(void* const* d_in, const int* in_sizes, int n_in,
                              void* d_out, int out_size) {
    const float* x  = (const float*)d_in[0];
    const float* rw = (const float*)d_in[1];
    const float* rb = (const float*)d_in[2];
    const float* w1 = (const float*)d_in[3];
    const float* w2 = (const float*)d_in[4];
    float* out = (float*)d_out;

    static bool attr_set = false;
    if (!attr_set) {
        cudaFuncSetAttribute((const void*)k_gemm_cp<HDIM, FDIM, 1>,
                             cudaFuncAttributeMaxDynamicSharedMemorySize, SMEM_BYTES);
        cudaFuncSetAttribute((const void*)k_gemm_cp<FDIM, HDIM, 2>,
                             cudaFuncAttributeMaxDynamicSharedMemorySize, SMEM_BYTES);
        attr_set = true;
    }

    k_init<<<1, 32>>>();
    k_convert_x<<<(NTOK*HDIM/4 + 255)/256, 256>>>(x);
    {
        int n4 = NEXP * HDIM * FDIM / 4;
        __half* w1h_p; cudaGetSymbolAddress((void**)&w1h_p, g_w1h);
        __half* w2h_p; cudaGetSymbolAddress((void**)&w2h_p, g_w2h);
        k_convert_w<<<(n4 + 255)/256, 256>>>((const float4*)w1, (uint2*)w1h_p, n4);
        k_convert_w<<<(n4 + 255)/256, 256>>>((const float4*)w2, (uint2*)w2h_p, n4);
    }
    k_router<<<NTOK/8, 256>>>(x, rw, rb);
    k_offsets<<<1, 1>>>();
    k_scatter<<<(NTOK*2 + 255)/256, 256>>>();

    k_gemm_cp<HDIM, FDIM, 1><<<136*32, 256, SMEM_BYTES>>>(nullptr);
    k_gemm_cp<FDIM, HDIM, 2><<<136*8, 256, SMEM_BYTES>>>(nullptr);

    k_combine<<<(NTOK*HDIM/4 + 255)/256, 256>>>(out);
}